// round 5
// baseline (speedup 1.0000x reference)
#include <cuda_runtime.h>
#include <math.h>

#define VSZ 8192
#define DSZ 128
#define NH 8
#define HDIM 16
#define NL 2
#define SQ 128
#define HID 341
#define EPSV 1e-6f

// Scratch (device globals: allocation-free)
__device__ float g_x[SQ*DSZ];
__device__ float g_q[SQ*DSZ];
__device__ float g_k[SQ*DSZ];
__device__ float g_v[SQ*DSZ];
__device__ float g_ao[SQ*DSZ];
__device__ float g_g[SQ*HID];
__device__ float g_xnT[DSZ*SQ];   // final normalized tokens, transposed [d][s]
__device__ float g_binv[VSZ];     // 1/||sigmoid col||
__device__ float g_bsum[VSZ];     // sum_d b_vd

__device__ __forceinline__ float sigmoidf_(float x) { return 1.0f/(1.0f + __expf(-x)); }

// ---------------- per-vocab column stats: inv-norm and Bsum ----------------
__global__ __launch_bounds__(256) void colnorm_kernel(const float* __restrict__ w_raw) {
    int v = blockIdx.x*256 + threadIdx.x;
    float ss = 0.0f, sq = 0.0f;
    #pragma unroll 4
    for (int d = 0; d < DSZ; d++) {
        float s = sigmoidf_(w_raw[d*VSZ + v]);
        ss += s; sq += s*s;
    }
    float inv = rsqrtf(sq);
    g_binv[v] = inv;
    g_bsum[v] = ss * inv;
}

// ---------------- embedding lookup ----------------
__global__ __launch_bounds__(256) void embed_kernel(const float* __restrict__ w_raw,
                                                    const int* __restrict__ idx) {
    int e = blockIdx.x*256 + threadIdx.x;      // 64 blocks -> 16384 elems
    int s = e >> 7, d = e & 127;
    int iv = idx[s];
    g_x[s*DSZ + d] = sigmoidf_(w_raw[d*VSZ + iv]);
}

// ---------------- QKV projection (+rms1, +rope) ----------------
// grid (8 row-tiles, 3 mats), 256 threads. 16 rows x 128 cols per block.
__global__ __launch_bounds__(256) void qkv_kernel(const float* __restrict__ wq,
                                                  const float* __restrict__ wk,
                                                  const float* __restrict__ wv,
                                                  const float* __restrict__ n1w, int layer) {
    __shared__ float xs[16][128];
    __shared__ float ws[32][128];
    __shared__ float ps[16][16];
    __shared__ float rs[16];
    int t = threadIdx.x;
    int mat = blockIdx.y;
    int row0 = blockIdx.x * 16;
    const float* W = (mat==0 ? wq : (mat==1 ? wk : wv)) + layer*DSZ*DSZ;
    const float* nw = n1w + layer*DSZ;

    for (int e = t; e < 2048; e += 256) xs[e>>7][e&127] = g_x[(row0 + (e>>7))*DSZ + (e&127)];
    __syncthreads();
    { // rmsnorm in place
        int r = t>>4, i = t&15;
        float sum = 0.0f;
        #pragma unroll
        for (int j = 0; j < 8; j++) { float vv = xs[r][i*8+j]; sum += vv*vv; }
        ps[r][i] = sum;
    }
    __syncthreads();
    if (t < 16) {
        float sum = 0.0f;
        #pragma unroll
        for (int i = 0; i < 16; i++) sum += ps[t][i];
        rs[t] = rsqrtf(sum * (1.0f/128.0f) + EPSV);
    }
    __syncthreads();
    {
        int r = t>>4, i = t&15;
        float sc = rs[r];
        #pragma unroll
        for (int j = 0; j < 8; j++) { int c = i*8+j; xs[r][c] = xs[r][c]*sc*nw[c]; }
    }
    __syncthreads();

    int r = t>>4;
    int c0 = (t&15)*8;
    float acc[8];
    #pragma unroll
    for (int j = 0; j < 8; j++) acc[j] = 0.0f;
    for (int kt = 0; kt < 128; kt += 32) {
        for (int f = t; f < 1024; f += 256) {
            int kk = f>>5, cc = (f&31)*4;
            *(float4*)&ws[kk][cc] = *(const float4*)&W[(kt+kk)*DSZ + cc];
        }
        __syncthreads();
        #pragma unroll
        for (int kk = 0; kk < 32; kk++) {
            float a = xs[r][kt+kk];
            float4 w0 = *(float4*)&ws[kk][c0];
            float4 w1 = *(float4*)&ws[kk][c0+4];
            acc[0] += a*w0.x; acc[1] += a*w0.y; acc[2] += a*w0.z; acc[3] += a*w0.w;
            acc[4] += a*w1.x; acc[5] += a*w1.y; acc[6] += a*w1.z; acc[7] += a*w1.w;
        }
        __syncthreads();
    }
    int i = row0 + r;
    float* out = (mat==0 ? g_q : (mat==1 ? g_k : g_v));
    if (mat < 2) { // rope on q,k
        #pragma unroll
        for (int p = 0; p < 4; p++) {
            int c = c0 + 2*p;
            int jj = (c & 15) >> 1;
            float inv = powf(10000.0f, -(float)jj * 0.125f);
            float ang = (float)i * inv;
            float sn_, cs_;
            sincosf(ang, &sn_, &cs_);
            float x0 = acc[2*p], x1 = acc[2*p+1];
            acc[2*p]   = x0*cs_ - x1*sn_;
            acc[2*p+1] = x0*sn_ + x1*cs_;
        }
    }
    #pragma unroll
    for (int j = 0; j < 8; j++) out[i*DSZ + c0 + j] = acc[j];
}

// ---------------- attention: one block per head, thread = query row ----------------
__global__ __launch_bounds__(128) void attn_kernel() {
    __shared__ float ks[128][16];
    __shared__ float vs[128][16];
    int t = threadIdx.x;
    int h = blockIdx.x;
    for (int e = t; e < 2048; e += 128) {
        int j = e>>4, c = e&15;
        ks[j][c] = g_k[j*DSZ + h*HDIM + c];
        vs[j][c] = g_v[j*DSZ + h*HDIM + c];
    }
    __syncthreads();
    int i = t;
    float q[16];
    const float4* qp = (const float4*)(g_q + i*DSZ + h*HDIM);
    #pragma unroll
    for (int p = 0; p < 4; p++) { float4 f = qp[p]; q[4*p]=f.x; q[4*p+1]=f.y; q[4*p+2]=f.z; q[4*p+3]=f.w; }
    float m = -1e30f, l = 0.0f;
    float o[16];
    #pragma unroll
    for (int c = 0; c < 16; c++) o[c] = 0.0f;
    for (int j = 0; j <= i; j++) {
        float s = 0.0f;
        #pragma unroll
        for (int c = 0; c < 16; c++) s += q[c]*ks[j][c];
        s *= 0.25f;
        float nm = fmaxf(m, s);
        float rf = __expf(m - nm);
        float p  = __expf(s - nm);
        l = l*rf + p;
        #pragma unroll
        for (int c = 0; c < 16; c++) o[c] = o[c]*rf + p*vs[j][c];
        m = nm;
    }
    float invl = 1.0f/l;
    #pragma unroll
    for (int c = 0; c < 16; c++) g_ao[i*DSZ + h*HDIM + c] = o[c]*invl;
}

// ---------------- O projection + residual ----------------
__global__ __launch_bounds__(256) void wo_kernel(const float* __restrict__ wo, int layer) {
    __shared__ float xs[16][128];
    __shared__ float ws[32][128];
    int t = threadIdx.x;
    int row0 = blockIdx.x * 16;
    const float* W = wo + layer*DSZ*DSZ;
    for (int e = t; e < 2048; e += 256) xs[e>>7][e&127] = g_ao[(row0 + (e>>7))*DSZ + (e&127)];
    __syncthreads();
    int r = t>>4, c0 = (t&15)*8;
    float acc[8];
    #pragma unroll
    for (int j = 0; j < 8; j++) acc[j] = 0.0f;
    for (int kt = 0; kt < 128; kt += 32) {
        for (int f = t; f < 1024; f += 256) {
            int kk = f>>5, cc = (f&31)*4;
            *(float4*)&ws[kk][cc] = *(const float4*)&W[(kt+kk)*DSZ + cc];
        }
        __syncthreads();
        #pragma unroll
        for (int kk = 0; kk < 32; kk++) {
            float a = xs[r][kt+kk];
            float4 w0 = *(float4*)&ws[kk][c0];
            float4 w1 = *(float4*)&ws[kk][c0+4];
            acc[0] += a*w0.x; acc[1] += a*w0.y; acc[2] += a*w0.z; acc[3] += a*w0.w;
            acc[4] += a*w1.x; acc[5] += a*w1.y; acc[6] += a*w1.z; acc[7] += a*w1.w;
        }
        __syncthreads();
    }
    int i = row0 + r;
    #pragma unroll
    for (int j = 0; j < 8; j++) g_x[i*DSZ + c0 + j] += acc[j];
}

// ---------------- FFN up (silu(h2@w1) * (h2@w3)), +rms2 ----------------
__global__ __launch_bounds__(256) void ffn1_kernel(const float* __restrict__ w1,
                                                   const float* __restrict__ w3,
                                                   const float* __restrict__ n2w, int layer) {
    __shared__ float xs[16][128];
    __shared__ float w1s[32][64];
    __shared__ float w3s[32][64];
    __shared__ float ps[16][16];
    __shared__ float rs[16];
    int t = threadIdx.x;
    int row0 = blockIdx.x * 16;
    const float* W1 = w1 + layer*DSZ*HID;
    const float* W3 = w3 + layer*DSZ*HID;
    const float* nw = n2w + layer*DSZ;

    for (int e = t; e < 2048; e += 256) xs[e>>7][e&127] = g_x[(row0 + (e>>7))*DSZ + (e&127)];
    __syncthreads();
    {
        int r = t>>4, i = t&15;
        float sum = 0.0f;
        #pragma unroll
        for (int j = 0; j < 8; j++) { float vv = xs[r][i*8+j]; sum += vv*vv; }
        ps[r][i] = sum;
    }
    __syncthreads();
    if (t < 16) {
        float sum = 0.0f;
        #pragma unroll
        for (int i = 0; i < 16; i++) sum += ps[t][i];
        rs[t] = rsqrtf(sum * (1.0f/128.0f) + EPSV);
    }
    __syncthreads();
    {
        int r = t>>4, i = t&15;
        float sc = rs[r];
        #pragma unroll
        for (int j = 0; j < 8; j++) { int c = i*8+j; xs[r][c] = xs[r][c]*sc*nw[c]; }
    }
    __syncthreads();

    int r = t>>4, cl0 = (t&15)*4;
    for (int ct = 0; ct < 6; ct++) {
        float a1[4] = {0,0,0,0}, a3[4] = {0,0,0,0};
        for (int kt = 0; kt < 128; kt += 32) {
            for (int f = t; f < 2048; f += 256) {
                int kk = f>>6, cc = f&63;
                int c = ct*64 + cc;
                float v1 = 0.0f, v3 = 0.0f;
                if (c < HID) { v1 = W1[(kt+kk)*HID + c]; v3 = W3[(kt+kk)*HID + c]; }
                w1s[kk][cc] = v1; w3s[kk][cc] = v3;
            }
            __syncthreads();
            #pragma unroll
            for (int kk = 0; kk < 32; kk++) {
                float a = xs[r][kt+kk];
                float4 u1 = *(float4*)&w1s[kk][cl0];
                float4 u3 = *(float4*)&w3s[kk][cl0];
                a1[0] += a*u1.x; a1[1] += a*u1.y; a1[2] += a*u1.z; a1[3] += a*u1.w;
                a3[0] += a*u3.x; a3[1] += a*u3.y; a3[2] += a*u3.z; a3[3] += a*u3.w;
            }
            __syncthreads();
        }
        #pragma unroll
        for (int j = 0; j < 4; j++) {
            int c = ct*64 + cl0 + j;
            if (c < HID) {
                float s1 = a1[j];
                g_g[(row0+r)*HID + c] = (s1 / (1.0f + __expf(-s1))) * a3[j];
            }
        }
    }
}

// ---------------- FFN down + residual ----------------
__global__ __launch_bounds__(256) void ffn2_kernel(const float* __restrict__ w2, int layer) {
    __shared__ float gs[16][HID];
    __shared__ float ws[31][128];
    int t = threadIdx.x;
    int row0 = blockIdx.x * 16;
    const float* W = w2 + layer*HID*DSZ;
    for (int e = t; e < 16*HID; e += 256) gs[e/HID][e%HID] = g_g[(row0 + e/HID)*HID + (e%HID)];
    __syncthreads();
    int r = t>>4, c0 = (t&15)*8;
    float acc[8];
    #pragma unroll
    for (int j = 0; j < 8; j++) acc[j] = 0.0f;
    for (int kt = 0; kt < HID; kt += 31) {
        for (int f = t; f < 992; f += 256) {
            int kk = f>>5, cc = (f&31)*4;
            *(float4*)&ws[kk][cc] = *(const float4*)&W[(kt+kk)*DSZ + cc];
        }
        __syncthreads();
        #pragma unroll
        for (int kk = 0; kk < 31; kk++) {
            float a = gs[r][kt+kk];
            float4 w0 = *(float4*)&ws[kk][c0];
            float4 w1 = *(float4*)&ws[kk][c0+4];
            acc[0] += a*w0.x; acc[1] += a*w0.y; acc[2] += a*w0.z; acc[3] += a*w0.w;
            acc[4] += a*w1.x; acc[5] += a*w1.y; acc[6] += a*w1.z; acc[7] += a*w1.w;
        }
        __syncthreads();
    }
    int i = row0 + r;
    #pragma unroll
    for (int j = 0; j < 8; j++) g_x[i*DSZ + c0 + j] += acc[j];
}

// ---------------- final rmsnorm + unit-normalize, write transposed ----------------
__global__ __launch_bounds__(256) void finalnorm_kernel(const float* __restrict__ fw) {
    __shared__ float xs[16][128];
    __shared__ float ps[16][16];
    __shared__ float rs[16];
    int t = threadIdx.x;
    int row0 = blockIdx.x * 16;
    for (int e = t; e < 2048; e += 256) xs[e>>7][e&127] = g_x[(row0 + (e>>7))*DSZ + (e&127)];
    __syncthreads();
    {
        int r = t>>4, i = t&15;
        float sum = 0.0f;
        #pragma unroll
        for (int j = 0; j < 8; j++) { float vv = xs[r][i*8+j]; sum += vv*vv; }
        ps[r][i] = sum;
    }
    __syncthreads();
    if (t < 16) {
        float sum = 0.0f;
        #pragma unroll
        for (int i = 0; i < 16; i++) sum += ps[t][i];
        rs[t] = rsqrtf(sum * (1.0f/128.0f) + EPSV);
    }
    __syncthreads();
    {
        int r = t>>4, i = t&15;
        float sc = rs[r];
        float sum2 = 0.0f;
        #pragma unroll
        for (int j = 0; j < 8; j++) {
            int c = i*8+j;
            float tv = xs[r][c]*sc*fw[c];
            xs[r][c] = tv;
            sum2 += tv*tv;
        }
        ps[r][i] = sum2;
    }
    __syncthreads();
    if (t < 16) {
        float sum = 0.0f;
        #pragma unroll
        for (int i = 0; i < 16; i++) sum += ps[t][i];
        rs[t] = rsqrtf(sum);
    }
    __syncthreads();
    {
        int r = t>>4, i = t&15;
        float sc = rs[r];
        int row = row0 + r;
        #pragma unroll
        for (int j = 0; j < 8; j++) {
            int c = i*8+j;
            g_xnT[c*SQ + row] = xs[r][c]*sc;
        }
    }
}

// ---------------- logits: mean_d( a<=b ? 1 : b ) = (Bsum + sum_{a<=b}(1-b))/128 ----------------
// grid 128 blocks (64-vocab tiles), 256 threads, each thread 4 tokens x 8 vocab.
__global__ __launch_bounds__(256) void logits_kernel(const float* __restrict__ w_raw,
                                                     float* __restrict__ out) {
    __shared__ float as_[16][128];
    __shared__ float bs[16][64];
    __shared__ float cs[16][64];
    int t = threadIdx.x;
    int v0 = blockIdx.x * 64;
    int sgrp = t >> 3, vgrp = t & 7;
    float acc[4][8];
    #pragma unroll
    for (int i = 0; i < 4; i++)
        #pragma unroll
        for (int j = 0; j < 8; j++) acc[i][j] = 0.0f;

    #pragma unroll 1
    for (int d0 = 0; d0 < 128; d0 += 16) {
        for (int e = t; e < 2048; e += 256) as_[e>>7][e&127] = g_xnT[(d0 + (e>>7))*SQ + (e&127)];
        for (int e = t; e < 1024; e += 256) {
            int dd = e>>6, vv = e&63;
            float b = sigmoidf_(w_raw[(d0+dd)*VSZ + v0 + vv]) * g_binv[v0+vv];
            bs[dd][vv] = b;
            cs[dd][vv] = 1.0f - b;
        }
        __syncthreads();
        #pragma unroll
        for (int dd = 0; dd < 16; dd++) {
            float4 av = *(float4*)&as_[dd][sgrp*4];
            float4 b0 = *(float4*)&bs[dd][vgrp*8];
            float4 b1 = *(float4*)&bs[dd][vgrp*8+4];
            float4 c0 = *(float4*)&cs[dd][vgrp*8];
            float4 c1 = *(float4*)&cs[dd][vgrp*8+4];
            float aa[4] = {av.x, av.y, av.z, av.w};
            float bb[8] = {b0.x,b0.y,b0.z,b0.w,b1.x,b1.y,b1.z,b1.w};
            float cc[8] = {c0.x,c0.y,c0.z,c0.w,c1.x,c1.y,c1.z,c1.w};
            #pragma unroll
            for (int i = 0; i < 4; i++)
                #pragma unroll
                for (int j = 0; j < 8; j++)
                    if (aa[i] <= bb[j]) acc[i][j] += cc[j];
        }
        __syncthreads();
    }
    #pragma unroll
    for (int i = 0; i < 4; i++) {
        int s = sgrp*4 + i;
        #pragma unroll
        for (int j = 0; j < 8; j++) {
            int v = v0 + vgrp*8 + j;
            float val = (acc[i][j] + g_bsum[v]) * (1.0f/128.0f);
            val = fminf(fmaxf(val, 1e-6f), 1.0f - 1e-6f);
            out[s*VSZ + v] = val;
        }
    }
}

extern "C" void kernel_launch(void* const* d_in, const int* in_sizes, int n_in,
                              void* d_out, int out_size) {
    (void)in_sizes; (void)n_in; (void)out_size;
    const int*   idx   = (const int*)  d_in[0];
    const float* w_raw = (const float*)d_in[1];
    const float* n1w   = (const float*)d_in[2];
    const float* n2w   = (const float*)d_in[3];
    const float* wq    = (const float*)d_in[4];
    const float* wk    = (const float*)d_in[5];
    const float* wv    = (const float*)d_in[6];
    const float* wo    = (const float*)d_in[7];
    const float* w1    = (const float*)d_in[8];
    const float* w3    = (const float*)d_in[9];   // setup_inputs dict order: w1, w3, w2
    const float* w2    = (const float*)d_in[10];
    const float* fw    = (const float*)d_in[11];
    float* out = (float*)d_out;

    colnorm_kernel<<<32, 256>>>(w_raw);
    embed_kernel<<<64, 256>>>(w_raw, idx);
    for (int l = 0; l < NL; l++) {
        qkv_kernel<<<dim3(8,3), 256>>>(wq, wk, wv, n1w, l);
        attn_kernel<<<8, 128>>>();
        wo_kernel<<<8, 256>>>(wo, l);
        ffn1_kernel<<<8, 256>>>(w1, w3, n2w, l);
        ffn2_kernel<<<8, 256>>>(w2, l);
    }
    finalnorm_kernel<<<8, 256>>>(fw);
    logits_kernel<<<128, 256>>>(w_raw, out);
}

// round 9
// speedup vs baseline: 2.0583x; 2.0583x over previous
#include <cuda_runtime.h>
#include <math.h>

#define VSZ 8192
#define DSZ 128
#define NH 8
#define HDIM 16
#define NL 2
#define SQ 128
#define HID 341
#define KP2 352
#define EPSV 1e-6f

// Scratch (device globals: allocation-free)
__device__ float g_x[SQ*DSZ];
__device__ float g_q[SQ*DSZ];
__device__ float g_k[SQ*DSZ];
__device__ float g_v[SQ*DSZ];
__device__ float g_ao[SQ*DSZ];
__device__ float g_g[SQ*HID];
__device__ float g_xnT[DSZ*SQ];   // final normalized tokens, transposed [d][s]
__device__ float g_binv[VSZ];     // 1/||sigmoid col||
__device__ float g_bsum[VSZ];     // sum_d b_vd

__device__ __forceinline__ float sigmoidf_(float x) { return 1.0f/(1.0f + __expf(-x)); }

// ---------------- per-vocab column stats: inv-norm and Bsum ----------------
__global__ __launch_bounds__(256) void colnorm_kernel(const float* __restrict__ w_raw) {
    int v = blockIdx.x*256 + threadIdx.x;
    float ss = 0.0f, sq = 0.0f;
    #pragma unroll 4
    for (int d = 0; d < DSZ; d++) {
        float s = sigmoidf_(w_raw[d*VSZ + v]);
        ss += s; sq += s*s;
    }
    float inv = rsqrtf(sq);
    g_binv[v] = inv;
    g_bsum[v] = ss * inv;
}

// ---------------- embedding lookup ----------------
__global__ __launch_bounds__(256) void embed_kernel(const float* __restrict__ w_raw,
                                                    const int* __restrict__ idx) {
    int e = blockIdx.x*256 + threadIdx.x;      // 64 blocks -> 16384 elems
    int s = e >> 7, d = e & 127;
    int iv = idx[s];
    g_x[s*DSZ + d] = sigmoidf_(w_raw[d*VSZ + iv]);
}

// ---------------- QKV projection (+rms1, +rope) ----------------
// grid (8 row-tiles, 6 = 3 mats x 2 col halves), 256 threads.
__global__ __launch_bounds__(256) void qkv_kernel(const float* __restrict__ wq,
                                                  const float* __restrict__ wk,
                                                  const float* __restrict__ wv,
                                                  const float* __restrict__ n1w, int layer) {
    __shared__ float xs[16][128];
    __shared__ float ws[32][64];
    __shared__ float ps[16][16];
    __shared__ float rs[16];
    int t = threadIdx.x;
    int mat = blockIdx.y >> 1;
    int col0 = (blockIdx.y & 1) * 64;
    int row0 = blockIdx.x * 16;
    const float* W = (mat==0 ? wq : (mat==1 ? wk : wv)) + layer*DSZ*DSZ;
    const float* nw = n1w + layer*DSZ;

    for (int e = t; e < 2048; e += 256) xs[e>>7][e&127] = g_x[(row0 + (e>>7))*DSZ + (e&127)];
    __syncthreads();
    { // rmsnorm in place
        int r = t>>4, i = t&15;
        float sum = 0.0f;
        #pragma unroll
        for (int j = 0; j < 8; j++) { float vv = xs[r][i*8+j]; sum += vv*vv; }
        ps[r][i] = sum;
    }
    __syncthreads();
    if (t < 16) {
        float sum = 0.0f;
        #pragma unroll
        for (int i = 0; i < 16; i++) sum += ps[t][i];
        rs[t] = rsqrtf(sum * (1.0f/128.0f) + EPSV);
    }
    __syncthreads();
    {
        int r = t>>4, i = t&15;
        float sc = rs[r];
        #pragma unroll
        for (int j = 0; j < 8; j++) { int c = i*8+j; xs[r][c] = xs[r][c]*sc*nw[c]; }
    }
    __syncthreads();

    int r = t>>4;
    int c4 = (t&15)*4;
    float acc[4] = {0,0,0,0};
    for (int kt = 0; kt < 128; kt += 32) {
        for (int f = t; f < 512; f += 256) {
            int kk = f>>4, cc = (f&15)*4;
            *(float4*)&ws[kk][cc] = *(const float4*)&W[(kt+kk)*DSZ + col0 + cc];
        }
        __syncthreads();
        #pragma unroll
        for (int kk = 0; kk < 32; kk++) {
            float a = xs[r][kt+kk];
            float4 w0 = *(float4*)&ws[kk][c4];
            acc[0] += a*w0.x; acc[1] += a*w0.y; acc[2] += a*w0.z; acc[3] += a*w0.w;
        }
        __syncthreads();
    }
    int i = row0 + r;
    float* out = (mat==0 ? g_q : (mat==1 ? g_k : g_v));
    int cg = col0 + c4;
    if (mat < 2) { // rope on q,k
        #pragma unroll
        for (int p = 0; p < 2; p++) {
            int c = cg + 2*p;
            int jj = (c & 15) >> 1;
            float inv = __powf(10000.0f, -(float)jj * 0.125f);
            float ang = (float)i * inv;
            float sn_, cs_;
            __sincosf(ang, &sn_, &cs_);
            float x0 = acc[2*p], x1 = acc[2*p+1];
            acc[2*p]   = x0*cs_ - x1*sn_;
            acc[2*p+1] = x0*sn_ + x1*cs_;
        }
    }
    #pragma unroll
    for (int j = 0; j < 4; j++) out[i*DSZ + cg + j] = acc[j];
}

// ---------------- attention: grid (8 heads, 8 query tiles), 128 threads ----------------
// 8-lane group per query row; 16 keys per lane; shfl reductions.
__global__ __launch_bounds__(128) void attn_kernel() {
    __shared__ float ks[128][20];   // pad 20: 8-lane stride-8 float4 access is conflict-free
    __shared__ float vs[128][20];
    int t = threadIdx.x;
    int h = blockIdx.x;
    int qt = blockIdx.y;
    for (int e = t; e < 2048; e += 128) {
        int j = e>>4, c = e&15;
        ks[j][c] = g_k[j*DSZ + h*HDIM + c];
        vs[j][c] = g_v[j*DSZ + h*HDIM + c];
    }
    __syncthreads();
    int tq = t >> 3, tk = t & 7;
    int i = qt*16 + tq;
    float4 q0, q1, q2, q3;
    {
        const float4* qp = (const float4*)(g_q + i*DSZ + h*HDIM);
        q0 = qp[0]; q1 = qp[1]; q2 = qp[2]; q3 = qp[3];
    }
    float s[16];
    float mloc = -1e30f;
    #pragma unroll
    for (int n = 0; n < 16; n++) {
        int j = tk + n*8;
        float sv = -1e30f;
        if (j <= i) {
            float4 k0 = *(float4*)&ks[j][0];
            float4 k1 = *(float4*)&ks[j][4];
            float4 k2 = *(float4*)&ks[j][8];
            float4 k3 = *(float4*)&ks[j][12];
            float d = q0.x*k0.x + q0.y*k0.y + q0.z*k0.z + q0.w*k0.w
                    + q1.x*k1.x + q1.y*k1.y + q1.z*k1.z + q1.w*k1.w
                    + q2.x*k2.x + q2.y*k2.y + q2.z*k2.z + q2.w*k2.w
                    + q3.x*k3.x + q3.y*k3.y + q3.z*k3.z + q3.w*k3.w;
            sv = d * 0.25f;
        }
        s[n] = sv;
        mloc = fmaxf(mloc, sv);
    }
    mloc = fmaxf(mloc, __shfl_xor_sync(0xFFFFFFFFu, mloc, 1));
    mloc = fmaxf(mloc, __shfl_xor_sync(0xFFFFFFFFu, mloc, 2));
    mloc = fmaxf(mloc, __shfl_xor_sync(0xFFFFFFFFu, mloc, 4));
    float lsum = 0.0f;
    #pragma unroll
    for (int n = 0; n < 16; n++) {
        int j = tk + n*8;
        float pv = 0.0f;
        if (j <= i) pv = __expf(s[n] - mloc);
        s[n] = pv;
        lsum += pv;
    }
    lsum += __shfl_xor_sync(0xFFFFFFFFu, lsum, 1);
    lsum += __shfl_xor_sync(0xFFFFFFFFu, lsum, 2);
    lsum += __shfl_xor_sync(0xFFFFFFFFu, lsum, 4);
    float o16[16];
    #pragma unroll
    for (int c = 0; c < 16; c++) o16[c] = 0.0f;
    #pragma unroll
    for (int n = 0; n < 16; n++) {
        int j = tk + n*8;
        if (j <= i) {
            float pv = s[n];
            float4 v0 = *(float4*)&vs[j][0];
            float4 v1 = *(float4*)&vs[j][4];
            float4 v2 = *(float4*)&vs[j][8];
            float4 v3 = *(float4*)&vs[j][12];
            o16[0]+=pv*v0.x; o16[1]+=pv*v0.y; o16[2]+=pv*v0.z; o16[3]+=pv*v0.w;
            o16[4]+=pv*v1.x; o16[5]+=pv*v1.y; o16[6]+=pv*v1.z; o16[7]+=pv*v1.w;
            o16[8]+=pv*v2.x; o16[9]+=pv*v2.y; o16[10]+=pv*v2.z; o16[11]+=pv*v2.w;
            o16[12]+=pv*v3.x; o16[13]+=pv*v3.y; o16[14]+=pv*v3.z; o16[15]+=pv*v3.w;
        }
    }
    #pragma unroll
    for (int c = 0; c < 16; c++) {
        float v = o16[c];
        v += __shfl_xor_sync(0xFFFFFFFFu, v, 1);
        v += __shfl_xor_sync(0xFFFFFFFFu, v, 2);
        v += __shfl_xor_sync(0xFFFFFFFFu, v, 4);
        o16[c] = v;
    }
    float invl = 1.0f / lsum;
    g_ao[i*DSZ + h*HDIM + 2*tk    ] = o16[2*tk]   * invl;
    g_ao[i*DSZ + h*HDIM + 2*tk + 1] = o16[2*tk+1] * invl;
}

// ---------------- O projection + residual: grid (8, 2) ----------------
__global__ __launch_bounds__(256) void wo_kernel(const float* __restrict__ wo, int layer) {
    __shared__ float xs[16][128];
    __shared__ float ws[32][64];
    int t = threadIdx.x;
    int row0 = blockIdx.x * 16;
    int col0 = blockIdx.y * 64;
    const float* W = wo + layer*DSZ*DSZ;
    for (int e = t; e < 2048; e += 256) xs[e>>7][e&127] = g_ao[(row0 + (e>>7))*DSZ + (e&127)];
    __syncthreads();
    int r = t>>4, c4 = (t&15)*4;
    float acc[4] = {0,0,0,0};
    for (int kt = 0; kt < 128; kt += 32) {
        for (int f = t; f < 512; f += 256) {
            int kk = f>>4, cc = (f&15)*4;
            *(float4*)&ws[kk][cc] = *(const float4*)&W[(kt+kk)*DSZ + col0 + cc];
        }
        __syncthreads();
        #pragma unroll
        for (int kk = 0; kk < 32; kk++) {
            float a = xs[r][kt+kk];
            float4 w0 = *(float4*)&ws[kk][c4];
            acc[0] += a*w0.x; acc[1] += a*w0.y; acc[2] += a*w0.z; acc[3] += a*w0.w;
        }
        __syncthreads();
    }
    int i = row0 + r;
    #pragma unroll
    for (int j = 0; j < 4; j++) g_x[i*DSZ + col0 + c4 + j] += acc[j];
}

// ---------------- FFN up: grid (8, 6 col-tiles), +rms2 ----------------
__global__ __launch_bounds__(256) void ffn1_kernel(const float* __restrict__ w1,
                                                   const float* __restrict__ w3,
                                                   const float* __restrict__ n2w, int layer) {
    __shared__ float xs[16][128];
    __shared__ float w1s[32][64];
    __shared__ float w3s[32][64];
    __shared__ float ps[16][16];
    __shared__ float rs[16];
    int t = threadIdx.x;
    int row0 = blockIdx.x * 16;
    int ct = blockIdx.y;
    const float* W1 = w1 + layer*DSZ*HID;
    const float* W3 = w3 + layer*DSZ*HID;
    const float* nw = n2w + layer*DSZ;

    for (int e = t; e < 2048; e += 256) xs[e>>7][e&127] = g_x[(row0 + (e>>7))*DSZ + (e&127)];
    __syncthreads();
    {
        int r = t>>4, i = t&15;
        float sum = 0.0f;
        #pragma unroll
        for (int j = 0; j < 8; j++) { float vv = xs[r][i*8+j]; sum += vv*vv; }
        ps[r][i] = sum;
    }
    __syncthreads();
    if (t < 16) {
        float sum = 0.0f;
        #pragma unroll
        for (int i = 0; i < 16; i++) sum += ps[t][i];
        rs[t] = rsqrtf(sum * (1.0f/128.0f) + EPSV);
    }
    __syncthreads();
    {
        int r = t>>4, i = t&15;
        float sc = rs[r];
        #pragma unroll
        for (int j = 0; j < 8; j++) { int c = i*8+j; xs[r][c] = xs[r][c]*sc*nw[c]; }
    }
    __syncthreads();

    int r = t>>4, cl0 = (t&15)*4;
    float a1[4] = {0,0,0,0}, a3[4] = {0,0,0,0};
    for (int kt = 0; kt < 128; kt += 32) {
        for (int f = t; f < 2048; f += 256) {
            int kk = f>>6, cc = f&63;
            int c = ct*64 + cc;
            float v1 = 0.0f, v3 = 0.0f;
            if (c < HID) { v1 = W1[(kt+kk)*HID + c]; v3 = W3[(kt+kk)*HID + c]; }
            w1s[kk][cc] = v1; w3s[kk][cc] = v3;
        }
        __syncthreads();
        #pragma unroll
        for (int kk = 0; kk < 32; kk++) {
            float a = xs[r][kt+kk];
            float4 u1 = *(float4*)&w1s[kk][cl0];
            float4 u3 = *(float4*)&w3s[kk][cl0];
            a1[0] += a*u1.x; a1[1] += a*u1.y; a1[2] += a*u1.z; a1[3] += a*u1.w;
            a3[0] += a*u3.x; a3[1] += a*u3.y; a3[2] += a*u3.z; a3[3] += a*u3.w;
        }
        __syncthreads();
    }
    #pragma unroll
    for (int j = 0; j < 4; j++) {
        int c = ct*64 + cl0 + j;
        if (c < HID) {
            float s1 = a1[j];
            g_g[(row0+r)*HID + c] = (s1 / (1.0f + __expf(-s1))) * a3[j];
        }
    }
}

// ---------------- FFN down + residual: grid (8, 2) ----------------
__global__ __launch_bounds__(256) void ffn2_kernel(const float* __restrict__ w2, int layer) {
    __shared__ float gs[16][KP2];
    __shared__ float ws[32][64];
    int t = threadIdx.x;
    int row0 = blockIdx.x * 16;
    int col0 = blockIdx.y * 64;
    const float* W = w2 + layer*HID*DSZ;
    for (int e = t; e < 16*KP2; e += 256) {
        int r = e / KP2, c = e % KP2;
        gs[r][c] = (c < HID) ? g_g[(row0 + r)*HID + c] : 0.0f;
    }
    __syncthreads();
    int r = t>>4, c4 = (t&15)*4;
    float acc[4] = {0,0,0,0};
    for (int kt = 0; kt < KP2; kt += 32) {
        for (int f = t; f < 512; f += 256) {
            int kk = f>>4, cc = (f&15)*4;
            int row = kt + kk;
            float4 v = make_float4(0.f,0.f,0.f,0.f);
            if (row < HID) v = *(const float4*)&W[row*DSZ + col0 + cc];
            *(float4*)&ws[kk][cc] = v;
        }
        __syncthreads();
        #pragma unroll
        for (int kk = 0; kk < 32; kk++) {
            float a = gs[r][kt+kk];
            float4 w0 = *(float4*)&ws[kk][c4];
            acc[0] += a*w0.x; acc[1] += a*w0.y; acc[2] += a*w0.z; acc[3] += a*w0.w;
        }
        __syncthreads();
    }
    int i = row0 + r;
    #pragma unroll
    for (int j = 0; j < 4; j++) g_x[i*DSZ + col0 + c4 + j] += acc[j];
}

// ---------------- final rmsnorm + unit-normalize, write transposed ----------------
__global__ __launch_bounds__(256) void finalnorm_kernel(const float* __restrict__ fw) {
    __shared__ float xs[16][128];
    __shared__ float ps[16][16];
    __shared__ float rs[16];
    int t = threadIdx.x;
    int row0 = blockIdx.x * 16;
    for (int e = t; e < 2048; e += 256) xs[e>>7][e&127] = g_x[(row0 + (e>>7))*DSZ + (e&127)];
    __syncthreads();
    {
        int r = t>>4, i = t&15;
        float sum = 0.0f;
        #pragma unroll
        for (int j = 0; j < 8; j++) { float vv = xs[r][i*8+j]; sum += vv*vv; }
        ps[r][i] = sum;
    }
    __syncthreads();
    if (t < 16) {
        float sum = 0.0f;
        #pragma unroll
        for (int i = 0; i < 16; i++) sum += ps[t][i];
        rs[t] = rsqrtf(sum * (1.0f/128.0f) + EPSV);
    }
    __syncthreads();
    {
        int r = t>>4, i = t&15;
        float sc = rs[r];
        float sum2 = 0.0f;
        #pragma unroll
        for (int j = 0; j < 8; j++) {
            int c = i*8+j;
            float tv = xs[r][c]*sc*fw[c];
            xs[r][c] = tv;
            sum2 += tv*tv;
        }
        ps[r][i] = sum2;
    }
    __syncthreads();
    if (t < 16) {
        float sum = 0.0f;
        #pragma unroll
        for (int i = 0; i < 16; i++) sum += ps[t][i];
        rs[t] = rsqrtf(sum);
    }
    __syncthreads();
    {
        int r = t>>4, i = t&15;
        float sc = rs[r];
        int row = row0 + r;
        #pragma unroll
        for (int j = 0; j < 8; j++) {
            int c = i*8+j;
            g_xnT[c*SQ + row] = xs[r][c]*sc;
        }
    }
}

// ---------------- logits: mean_d( a<=b ? 1 : b ) = (Bsum + sum_{a<=b}(1-b))/128 ----------------
__global__ __launch_bounds__(256) void logits_kernel(const float* __restrict__ w_raw,
                                                     float* __restrict__ out) {
    __shared__ float as_[16][128];
    __shared__ float bs[16][64];
    __shared__ float cs[16][64];
    int t = threadIdx.x;
    int v0 = blockIdx.x * 64;
    int sgrp = t >> 3, vgrp = t & 7;
    float acc[4][8];
    #pragma unroll
    for (int i = 0; i < 4; i++)
        #pragma unroll
        for (int j = 0; j < 8; j++) acc[i][j] = 0.0f;

    #pragma unroll 1
    for (int d0 = 0; d0 < 128; d0 += 16) {
        for (int e = t; e < 2048; e += 256) as_[e>>7][e&127] = g_xnT[(d0 + (e>>7))*SQ + (e&127)];
        for (int e = t; e < 1024; e += 256) {
            int dd = e>>6, vv = e&63;
            float b = sigmoidf_(w_raw[(d0+dd)*VSZ + v0 + vv]) * g_binv[v0+vv];
            bs[dd][vv] = b;
            cs[dd][vv] = 1.0f - b;
        }
        __syncthreads();
        #pragma unroll
        for (int dd = 0; dd < 16; dd++) {
            float4 av = *(float4*)&as_[dd][sgrp*4];
            float4 b0 = *(float4*)&bs[dd][vgrp*8];
            float4 b1 = *(float4*)&bs[dd][vgrp*8+4];
            float4 c0 = *(float4*)&cs[dd][vgrp*8];
            float4 c1 = *(float4*)&cs[dd][vgrp*8+4];
            float aa[4] = {av.x, av.y, av.z, av.w};
            float bb[8] = {b0.x,b0.y,b0.z,b0.w,b1.x,b1.y,b1.z,b1.w};
            float cc[8] = {c0.x,c0.y,c0.z,c0.w,c1.x,c1.y,c1.z,c1.w};
            #pragma unroll
            for (int i = 0; i < 4; i++)
                #pragma unroll
                for (int j = 0; j < 8; j++)
                    if (aa[i] <= bb[j]) acc[i][j] += cc[j];
        }
        __syncthreads();
    }
    #pragma unroll
    for (int i = 0; i < 4; i++) {
        int s = sgrp*4 + i;
        #pragma unroll
        for (int j = 0; j < 8; j++) {
            int v = v0 + vgrp*8 + j;
            float val = (acc[i][j] + g_bsum[v]) * (1.0f/128.0f);
            val = fminf(fmaxf(val, 1e-6f), 1.0f - 1e-6f);
            out[s*VSZ + v] = val;
        }
    }
}

extern "C" void kernel_launch(void* const* d_in, const int* in_sizes, int n_in,
                              void* d_out, int out_size) {
    (void)in_sizes; (void)n_in; (void)out_size;
    const int*   idx   = (const int*)  d_in[0];
    const float* w_raw = (const float*)d_in[1];
    const float* n1w   = (const float*)d_in[2];
    const float* n2w   = (const float*)d_in[3];
    const float* wq    = (const float*)d_in[4];
    const float* wk    = (const float*)d_in[5];
    const float* wv    = (const float*)d_in[6];
    const float* wo    = (const float*)d_in[7];
    const float* w1    = (const float*)d_in[8];
    const float* w3    = (const float*)d_in[9];
    const float* w2    = (const float*)d_in[10];
    const float* fw    = (const float*)d_in[11];
    float* out = (float*)d_out;

    colnorm_kernel<<<32, 256>>>(w_raw);
    embed_kernel<<<64, 256>>>(w_raw, idx);
    for (int l = 0; l < NL; l++) {
        qkv_kernel<<<dim3(8,6), 256>>>(wq, wk, wv, n1w, l);
        attn_kernel<<<dim3(8,8), 128>>>();
        wo_kernel<<<dim3(8,2), 256>>>(wo, l);
        ffn1_kernel<<<dim3(8,6), 256>>>(w1, w3, n2w, l);
        ffn2_kernel<<<dim3(8,2), 256>>>(w2, l);
    }
    finalnorm_kernel<<<8, 256>>>(fw);
    logits_kernel<<<128, 256>>>(w_raw, out);
}

// round 12
// speedup vs baseline: 2.1469x; 1.0430x over previous
#include <cuda_runtime.h>
#include <math.h>

#define VSZ 8192
#define DSZ 128
#define NH 8
#define HDIM 16
#define NL 2
#define SQ 128
#define HID 341
#define KP2 352
#define EPSV 1e-6f
#define NBLK 48

// Scratch (device globals: allocation-free)
__device__ float g_x[SQ*DSZ];
__device__ float g_q[SQ*DSZ];
__device__ float g_k[SQ*DSZ];
__device__ float g_v[SQ*DSZ];
__device__ float g_ao[SQ*DSZ];
__device__ float g_g[SQ*HID];
__device__ float g_xnT[DSZ*SQ];   // final normalized tokens, transposed [d][s]
__device__ float g_binv[VSZ];     // 1/||sigmoid col||
__device__ float g_bsum[VSZ];     // sum_d b_vd

// Software grid barrier state (sense-reversing; self-resetting across replays)
__device__ unsigned g_bar_count = 0;
__device__ unsigned g_bar_gen = 0;

__device__ __forceinline__ void grid_sync() {
    __syncthreads();
    if (threadIdx.x == 0) {
        __threadfence();
        unsigned gen = *(volatile unsigned*)&g_bar_gen;
        unsigned arrived = atomicAdd(&g_bar_count, 1u);
        if (arrived == NBLK - 1u) {
            atomicExch(&g_bar_count, 0u);
            __threadfence();
            atomicAdd(&g_bar_gen, 1u);
        } else {
            while (*(volatile unsigned*)&g_bar_gen == gen) { __nanosleep(32); }
        }
        __threadfence();
    }
    __syncthreads();
}

__device__ __forceinline__ float sigmoidf_(float x) { return 1.0f/(1.0f + __expf(-x)); }

// =====================================================================
// Fused transformer: colnorm+embed -> (qkv, attn, wo, ffn1, ffn2) x L -> finalnorm
// grid NBLK=48 blocks x 256 threads, software grid barriers between phases.
// =====================================================================
__global__ __launch_bounds__(256) void fused_kernel(
    const int* __restrict__ idx,
    const float* __restrict__ w_raw,
    const float* __restrict__ n1w,
    const float* __restrict__ n2w,
    const float* __restrict__ wq,
    const float* __restrict__ wk,
    const float* __restrict__ wv,
    const float* __restrict__ wo,
    const float* __restrict__ w1,
    const float* __restrict__ w3,
    const float* __restrict__ w2,
    const float* __restrict__ fw)
{
    __shared__ __align__(16) float smem_f[10240];   // 40KB union, per-phase layouts
    const int t = threadIdx.x;
    const int b = blockIdx.x;

    // ---------------- phase 0: colnorm + embed (grid-strided) ----------------
    for (int v = b*256 + t; v < VSZ; v += NBLK*256) {
        float ss = 0.0f, sq = 0.0f;
        #pragma unroll 4
        for (int d = 0; d < DSZ; d++) {
            float s = sigmoidf_(w_raw[d*VSZ + v]);
            ss += s; sq += s*s;
        }
        float inv = rsqrtf(sq);
        g_binv[v] = inv;
        g_bsum[v] = ss * inv;
    }
    for (int e = b*256 + t; e < SQ*DSZ; e += NBLK*256) {
        int s = e >> 7, d = e & 127;
        g_x[s*DSZ + d] = sigmoidf_(w_raw[d*VSZ + idx[s]]);
    }
    grid_sync();

    for (int layer = 0; layer < NL; layer++) {
        // ---------------- qkv (+rms1, +rope): 48 units ----------------
        {
            float (*xs)[128] = (float(*)[128])smem_f;
            float (*ws)[64]  = (float(*)[64])(smem_f + 2048);
            float (*ps)[16]  = (float(*)[16])(smem_f + 4096);
            float *rs        = smem_f + 4352;
            int y = b >> 3;
            int mat = y >> 1;
            int col0 = (y & 1) * 64;
            int row0 = (b & 7) * 16;
            const float* W = (mat==0 ? wq : (mat==1 ? wk : wv)) + layer*DSZ*DSZ;
            const float* nw = n1w + layer*DSZ;

            for (int e = t; e < 2048; e += 256) xs[e>>7][e&127] = g_x[(row0 + (e>>7))*DSZ + (e&127)];
            __syncthreads();
            {
                int r = t>>4, i = t&15;
                float sum = 0.0f;
                #pragma unroll
                for (int j = 0; j < 8; j++) { float vv = xs[r][i*8+j]; sum += vv*vv; }
                ps[r][i] = sum;
            }
            __syncthreads();
            if (t < 16) {
                float sum = 0.0f;
                #pragma unroll
                for (int i = 0; i < 16; i++) sum += ps[t][i];
                rs[t] = rsqrtf(sum * (1.0f/128.0f) + EPSV);
            }
            __syncthreads();
            {
                int r = t>>4, i = t&15;
                float sc = rs[r];
                #pragma unroll
                for (int j = 0; j < 8; j++) { int c = i*8+j; xs[r][c] = xs[r][c]*sc*nw[c]; }
            }
            __syncthreads();

            int r = t>>4;
            int c4 = (t&15)*4;
            float acc[4] = {0,0,0,0};
            for (int kt = 0; kt < 128; kt += 32) {
                for (int f = t; f < 512; f += 256) {
                    int kk = f>>4, cc = (f&15)*4;
                    *(float4*)&ws[kk][cc] = *(const float4*)&W[(kt+kk)*DSZ + col0 + cc];
                }
                __syncthreads();
                #pragma unroll
                for (int kk = 0; kk < 32; kk++) {
                    float a = xs[r][kt+kk];
                    float4 w0 = *(float4*)&ws[kk][c4];
                    acc[0] += a*w0.x; acc[1] += a*w0.y; acc[2] += a*w0.z; acc[3] += a*w0.w;
                }
                __syncthreads();
            }
            int i = row0 + r;
            float* out = (mat==0 ? g_q : (mat==1 ? g_k : g_v));
            int cg = col0 + c4;
            if (mat < 2) { // rope on q,k
                #pragma unroll
                for (int p = 0; p < 2; p++) {
                    int c = cg + 2*p;
                    int jj = (c & 15) >> 1;
                    float inv = __powf(10000.0f, -(float)jj * 0.125f);
                    float ang = (float)i * inv;
                    float sn_, cs_;
                    __sincosf(ang, &sn_, &cs_);
                    float x0 = acc[2*p], x1 = acc[2*p+1];
                    acc[2*p]   = x0*cs_ - x1*sn_;
                    acc[2*p+1] = x0*sn_ + x1*cs_;
                }
            }
            #pragma unroll
            for (int j = 0; j < 4; j++) out[i*DSZ + cg + j] = acc[j];
        }
        grid_sync();

        // ---------------- attention: 64 units; blocks 0..31 run 2 units each ----------------
        if (b < 32) {
            int sub = t >> 7;
            int tt = t & 127;
            int unit = b*2 + sub;
            int h = unit & 7;
            int qt = unit >> 3;
            float (*ks)[20] = (float(*)[20])(smem_f + sub*5120);
            float (*vs)[20] = (float(*)[20])(smem_f + sub*5120 + 2560);
            for (int e = tt; e < 2048; e += 128) {
                int j = e>>4, c = e&15;
                ks[j][c] = g_k[j*DSZ + h*HDIM + c];
                vs[j][c] = g_v[j*DSZ + h*HDIM + c];
            }
            __syncthreads();
            int tq = tt >> 3, tk = tt & 7;
            int i = qt*16 + tq;
            float4 q0, q1, q2, q3;
            {
                const float4* qp = (const float4*)(g_q + i*DSZ + h*HDIM);
                q0 = qp[0]; q1 = qp[1]; q2 = qp[2]; q3 = qp[3];
            }
            float s[16];
            float mloc = -1e30f;
            #pragma unroll
            for (int n = 0; n < 16; n++) {
                int j = tk + n*8;
                float sv = -1e30f;
                if (j <= i) {
                    float4 k0 = *(float4*)&ks[j][0];
                    float4 k1 = *(float4*)&ks[j][4];
                    float4 k2 = *(float4*)&ks[j][8];
                    float4 k3 = *(float4*)&ks[j][12];
                    float d = q0.x*k0.x + q0.y*k0.y + q0.z*k0.z + q0.w*k0.w
                            + q1.x*k1.x + q1.y*k1.y + q1.z*k1.z + q1.w*k1.w
                            + q2.x*k2.x + q2.y*k2.y + q2.z*k2.z + q2.w*k2.w
                            + q3.x*k3.x + q3.y*k3.y + q3.z*k3.z + q3.w*k3.w;
                    sv = d * 0.25f;
                }
                s[n] = sv;
                mloc = fmaxf(mloc, sv);
            }
            mloc = fmaxf(mloc, __shfl_xor_sync(0xFFFFFFFFu, mloc, 1));
            mloc = fmaxf(mloc, __shfl_xor_sync(0xFFFFFFFFu, mloc, 2));
            mloc = fmaxf(mloc, __shfl_xor_sync(0xFFFFFFFFu, mloc, 4));
            float lsum = 0.0f;
            #pragma unroll
            for (int n = 0; n < 16; n++) {
                int j = tk + n*8;
                float pv = 0.0f;
                if (j <= i) pv = __expf(s[n] - mloc);
                s[n] = pv;
                lsum += pv;
            }
            lsum += __shfl_xor_sync(0xFFFFFFFFu, lsum, 1);
            lsum += __shfl_xor_sync(0xFFFFFFFFu, lsum, 2);
            lsum += __shfl_xor_sync(0xFFFFFFFFu, lsum, 4);
            float o16[16];
            #pragma unroll
            for (int c = 0; c < 16; c++) o16[c] = 0.0f;
            #pragma unroll
            for (int n = 0; n < 16; n++) {
                int j = tk + n*8;
                if (j <= i) {
                    float pv = s[n];
                    float4 v0 = *(float4*)&vs[j][0];
                    float4 v1 = *(float4*)&vs[j][4];
                    float4 v2 = *(float4*)&vs[j][8];
                    float4 v3 = *(float4*)&vs[j][12];
                    o16[0]+=pv*v0.x; o16[1]+=pv*v0.y; o16[2]+=pv*v0.z; o16[3]+=pv*v0.w;
                    o16[4]+=pv*v1.x; o16[5]+=pv*v1.y; o16[6]+=pv*v1.z; o16[7]+=pv*v1.w;
                    o16[8]+=pv*v2.x; o16[9]+=pv*v2.y; o16[10]+=pv*v2.z; o16[11]+=pv*v2.w;
                    o16[12]+=pv*v3.x; o16[13]+=pv*v3.y; o16[14]+=pv*v3.z; o16[15]+=pv*v3.w;
                }
            }
            #pragma unroll
            for (int c = 0; c < 16; c++) {
                float v = o16[c];
                v += __shfl_xor_sync(0xFFFFFFFFu, v, 1);
                v += __shfl_xor_sync(0xFFFFFFFFu, v, 2);
                v += __shfl_xor_sync(0xFFFFFFFFu, v, 4);
                o16[c] = v;
            }
            float invl = 1.0f / lsum;
            g_ao[i*DSZ + h*HDIM + 2*tk    ] = o16[2*tk]   * invl;
            g_ao[i*DSZ + h*HDIM + 2*tk + 1] = o16[2*tk+1] * invl;
        }
        grid_sync();

        // ---------------- O projection + residual: 16 units ----------------
        if (b < 16) {
            float (*xs)[128] = (float(*)[128])smem_f;
            float (*ws)[64]  = (float(*)[64])(smem_f + 2048);
            int row0 = (b >> 1) * 16;
            int col0 = (b & 1) * 64;
            const float* W = wo + layer*DSZ*DSZ;
            for (int e = t; e < 2048; e += 256) xs[e>>7][e&127] = g_ao[(row0 + (e>>7))*DSZ + (e&127)];
            __syncthreads();
            int r = t>>4, c4 = (t&15)*4;
            float acc[4] = {0,0,0,0};
            for (int kt = 0; kt < 128; kt += 32) {
                for (int f = t; f < 512; f += 256) {
                    int kk = f>>4, cc = (f&15)*4;
                    *(float4*)&ws[kk][cc] = *(const float4*)&W[(kt+kk)*DSZ + col0 + cc];
                }
                __syncthreads();
                #pragma unroll
                for (int kk = 0; kk < 32; kk++) {
                    float a = xs[r][kt+kk];
                    float4 w0 = *(float4*)&ws[kk][c4];
                    acc[0] += a*w0.x; acc[1] += a*w0.y; acc[2] += a*w0.z; acc[3] += a*w0.w;
                }
                __syncthreads();
            }
            int i = row0 + r;
            #pragma unroll
            for (int j = 0; j < 4; j++) g_x[i*DSZ + col0 + c4 + j] += acc[j];
        }
        grid_sync();

        // ---------------- FFN up (+rms2): 48 units ----------------
        {
            float (*xs)[128]  = (float(*)[128])smem_f;
            float (*w1s)[64]  = (float(*)[64])(smem_f + 2048);
            float (*w3s)[64]  = (float(*)[64])(smem_f + 4096);
            float (*ps)[16]   = (float(*)[16])(smem_f + 6144);
            float *rs         = smem_f + 6400;
            int row0 = (b & 7) * 16;
            int ct = b >> 3;
            const float* W1 = w1 + layer*DSZ*HID;
            const float* W3 = w3 + layer*DSZ*HID;
            const float* nw = n2w + layer*DSZ;

            for (int e = t; e < 2048; e += 256) xs[e>>7][e&127] = g_x[(row0 + (e>>7))*DSZ + (e&127)];
            __syncthreads();
            {
                int r = t>>4, i = t&15;
                float sum = 0.0f;
                #pragma unroll
                for (int j = 0; j < 8; j++) { float vv = xs[r][i*8+j]; sum += vv*vv; }
                ps[r][i] = sum;
            }
            __syncthreads();
            if (t < 16) {
                float sum = 0.0f;
                #pragma unroll
                for (int i = 0; i < 16; i++) sum += ps[t][i];
                rs[t] = rsqrtf(sum * (1.0f/128.0f) + EPSV);
            }
            __syncthreads();
            {
                int r = t>>4, i = t&15;
                float sc = rs[r];
                #pragma unroll
                for (int j = 0; j < 8; j++) { int c = i*8+j; xs[r][c] = xs[r][c]*sc*nw[c]; }
            }
            __syncthreads();

            int r = t>>4, cl0 = (t&15)*4;
            float a1[4] = {0,0,0,0}, a3[4] = {0,0,0,0};
            for (int kt = 0; kt < 128; kt += 32) {
                for (int f = t; f < 2048; f += 256) {
                    int kk = f>>6, cc = f&63;
                    int c = ct*64 + cc;
                    float v1 = 0.0f, v3 = 0.0f;
                    if (c < HID) { v1 = W1[(kt+kk)*HID + c]; v3 = W3[(kt+kk)*HID + c]; }
                    w1s[kk][cc] = v1; w3s[kk][cc] = v3;
                }
                __syncthreads();
                #pragma unroll
                for (int kk = 0; kk < 32; kk++) {
                    float a = xs[r][kt+kk];
                    float4 u1 = *(float4*)&w1s[kk][cl0];
                    float4 u3 = *(float4*)&w3s[kk][cl0];
                    a1[0] += a*u1.x; a1[1] += a*u1.y; a1[2] += a*u1.z; a1[3] += a*u1.w;
                    a3[0] += a*u3.x; a3[1] += a*u3.y; a3[2] += a*u3.z; a3[3] += a*u3.w;
                }
                __syncthreads();
            }
            #pragma unroll
            for (int j = 0; j < 4; j++) {
                int c = ct*64 + cl0 + j;
                if (c < HID) {
                    float s1 = a1[j];
                    g_g[(row0+r)*HID + c] = (s1 / (1.0f + __expf(-s1))) * a3[j];
                }
            }
        }
        grid_sync();

        // ---------------- FFN down + residual: 16 units ----------------
        if (b < 16) {
            float (*gs)[KP2] = (float(*)[KP2])smem_f;
            float (*ws)[64]  = (float(*)[64])(smem_f + 16*KP2);
            int row0 = (b >> 1) * 16;
            int col0 = (b & 1) * 64;
            const float* W = w2 + layer*HID*DSZ;
            for (int e = t; e < 16*KP2; e += 256) {
                int r = e / KP2, c = e % KP2;
                gs[r][c] = (c < HID) ? g_g[(row0 + r)*HID + c] : 0.0f;
            }
            __syncthreads();
            int r = t>>4, c4 = (t&15)*4;
            float acc[4] = {0,0,0,0};
            for (int kt = 0; kt < KP2; kt += 32) {
                for (int f = t; f < 512; f += 256) {
                    int kk = f>>4, cc = (f&15)*4;
                    int row = kt + kk;
                    float4 v = make_float4(0.f,0.f,0.f,0.f);
                    if (row < HID) v = *(const float4*)&W[row*DSZ + col0 + cc];
                    *(float4*)&ws[kk][cc] = v;
                }
                __syncthreads();
                #pragma unroll
                for (int kk = 0; kk < 32; kk++) {
                    float a = gs[r][kt+kk];
                    float4 w0 = *(float4*)&ws[kk][c4];
                    acc[0] += a*w0.x; acc[1] += a*w0.y; acc[2] += a*w0.z; acc[3] += a*w0.w;
                }
                __syncthreads();
            }
            int i = row0 + r;
            #pragma unroll
            for (int j = 0; j < 4; j++) g_x[i*DSZ + col0 + c4 + j] += acc[j];
        }
        grid_sync();
    }

    // ---------------- final rmsnorm + unit-normalize, write transposed: 8 units ----------------
    if (b < 8) {
        float (*xs)[128] = (float(*)[128])smem_f;
        float (*ps)[16]  = (float(*)[16])(smem_f + 2048);
        float *rs        = smem_f + 2304;
        int row0 = b * 16;
        for (int e = t; e < 2048; e += 256) xs[e>>7][e&127] = g_x[(row0 + (e>>7))*DSZ + (e&127)];
        __syncthreads();
        {
            int r = t>>4, i = t&15;
            float sum = 0.0f;
            #pragma unroll
            for (int j = 0; j < 8; j++) { float vv = xs[r][i*8+j]; sum += vv*vv; }
            ps[r][i] = sum;
        }
        __syncthreads();
        if (t < 16) {
            float sum = 0.0f;
            #pragma unroll
            for (int i = 0; i < 16; i++) sum += ps[t][i];
            rs[t] = rsqrtf(sum * (1.0f/128.0f) + EPSV);
        }
        __syncthreads();
        {
            int r = t>>4, i = t&15;
            float sc = rs[r];
            float sum2 = 0.0f;
            #pragma unroll
            for (int j = 0; j < 8; j++) {
                int c = i*8+j;
                float tv = xs[r][c]*sc*fw[c];
                xs[r][c] = tv;
                sum2 += tv*tv;
            }
            ps[r][i] = sum2;
        }
        __syncthreads();
        if (t < 16) {
            float sum = 0.0f;
            #pragma unroll
            for (int i = 0; i < 16; i++) sum += ps[t][i];
            rs[t] = rsqrtf(sum);
        }
        __syncthreads();
        {
            int r = t>>4, i = t&15;
            float sc = rs[r];
            int row = row0 + r;
            #pragma unroll
            for (int j = 0; j < 8; j++) {
                int c = i*8+j;
                g_xnT[c*SQ + row] = xs[r][c]*sc;
            }
        }
    }
}

// ---------------- logits: mean_d( a<=b ? 1 : b ) = (Bsum + sum_{a<=b}(1-b))/128 ----------------
__global__ __launch_bounds__(256) void logits_kernel(const float* __restrict__ w_raw,
                                                     float* __restrict__ out) {
    __shared__ float as_[16][128];
    __shared__ float bs[16][64];
    __shared__ float cs[16][64];
    int t = threadIdx.x;
    int v0 = blockIdx.x * 64;
    int sgrp = t >> 3, vgrp = t & 7;
    float acc[4][8];
    #pragma unroll
    for (int i = 0; i < 4; i++)
        #pragma unroll
        for (int j = 0; j < 8; j++) acc[i][j] = 0.0f;

    #pragma unroll 1
    for (int d0 = 0; d0 < 128; d0 += 16) {
        for (int e = t; e < 2048; e += 256) as_[e>>7][e&127] = g_xnT[(d0 + (e>>7))*SQ + (e&127)];
        for (int e = t; e < 1024; e += 256) {
            int dd = e>>6, vv = e&63;
            float b = sigmoidf_(w_raw[(d0+dd)*VSZ + v0 + vv]) * g_binv[v0+vv];
            bs[dd][vv] = b;
            cs[dd][vv] = 1.0f - b;
        }
        __syncthreads();
        #pragma unroll
        for (int dd = 0; dd < 16; dd++) {
            float4 av = *(float4*)&as_[dd][sgrp*4];
            float4 b0 = *(float4*)&bs[dd][vgrp*8];
            float4 b1 = *(float4*)&bs[dd][vgrp*8+4];
            float4 c0 = *(float4*)&cs[dd][vgrp*8];
            float4 c1 = *(float4*)&cs[dd][vgrp*8+4];
            float aa[4] = {av.x, av.y, av.z, av.w};
            float bb[8] = {b0.x,b0.y,b0.z,b0.w,b1.x,b1.y,b1.z,b1.w};
            float cc[8] = {c0.x,c0.y,c0.z,c0.w,c1.x,c1.y,c1.z,c1.w};
            #pragma unroll
            for (int i = 0; i < 4; i++)
                #pragma unroll
                for (int j = 0; j < 8; j++)
                    if (aa[i] <= bb[j]) acc[i][j] += cc[j];
        }
        __syncthreads();
    }
    #pragma unroll
    for (int i = 0; i < 4; i++) {
        int s = sgrp*4 + i;
        #pragma unroll
        for (int j = 0; j < 8; j++) {
            int v = v0 + vgrp*8 + j;
            float val = (acc[i][j] + g_bsum[v]) * (1.0f/128.0f);
            val = fminf(fmaxf(val, 1e-6f), 1.0f - 1e-6f);
            out[s*VSZ + v] = val;
        }
    }
}

extern "C" void kernel_launch(void* const* d_in, const int* in_sizes, int n_in,
                              void* d_out, int out_size) {
    (void)in_sizes; (void)n_in; (void)out_size;
    const int*   idx   = (const int*)  d_in[0];
    const float* w_raw = (const float*)d_in[1];
    const float* n1w   = (const float*)d_in[2];
    const float* n2w   = (const float*)d_in[3];
    const float* wq    = (const float*)d_in[4];
    const float* wk    = (const float*)d_in[5];
    const float* wv    = (const float*)d_in[6];
    const float* wo    = (const float*)d_in[7];
    const float* w1    = (const float*)d_in[8];
    const float* w3    = (const float*)d_in[9];
    const float* w2    = (const float*)d_in[10];
    const float* fw    = (const float*)d_in[11];
    float* out = (float*)d_out;

    fused_kernel<<<NBLK, 256>>>(idx, w_raw, n1w, n2w, wq, wk, wv, wo, w1, w3, w2, fw);
    logits_kernel<<<128, 256>>>(w_raw, out);
}